// round 14
// baseline (speedup 1.0000x reference)
#include <cuda_runtime.h>
#include <cstdint>

// Problem shape (fixed for this dataset entry)
#define B_  4
#define C_  32
#define H_  256
#define W_  512
#define D_  48
#define HW_ (H_ * W_)

#define WT  128              // w-tile per block
#define NTHREADS 256
#define MB  8                // m16-blocks per tile (one per warp)
#define KS  8                // k-steps (k8) per m-block: band 16+48 = 64 = 8*8
#define KCH 22               // distinct k8 chunks in window [0, 176)

// smem (dynamic): A-frag 8192 words + B-frag 8448 words = 66560 B
#define A_FLOATS 8192        // [MB][KS][32 lanes][4 slots]
#define B_STRIDE 12          // words per (chunk, lane) row: 8 payload + 4 pad
#define B_FLOATS (KCH * 32 * B_STRIDE)   // 8448
#define SMEM_BYTES ((A_FLOATS + B_FLOATS) * 4)

// fp32 -> tf32 (round-to-nearest) kept in b32 register
__device__ __forceinline__ unsigned tf32_of(float v) {
    unsigned r;
    asm("cvt.rna.tf32.f32 %0, %1;" : "=r"(r) : "f"(v));
    return r;
}

// D(16x8,f32) += A(16x8,tf32,row) * B(8x8,tf32,col)
__device__ __forceinline__ void mma8(float* d,
                                     unsigned a0, unsigned a1,
                                     unsigned a2, unsigned a3,
                                     unsigned b0, unsigned b1) {
    asm volatile(
        "mma.sync.aligned.m16n8k8.row.col.f32.tf32.tf32.f32 "
        "{%0,%1,%2,%3}, {%4,%5,%6,%7}, {%8,%9}, {%0,%1,%2,%3};"
        : "+f"(d[0]), "+f"(d[1]), "+f"(d[2]), "+f"(d[3])
        : "r"(a0), "r"(a1), "r"(a2), "r"(a3), "r"(b0), "r"(b1));
}

__global__ void __launch_bounds__(NTHREADS)
dense_warp_kernel(const float* __restrict__ h1,
                  const float* __restrict__ cost,
                  float* __restrict__ out) {
    extern __shared__ __align__(16) unsigned smu[];
    unsigned* Af = smu;                // A-frag region
    unsigned* Bf = smu + A_FLOATS;     // B-frag region

    const int bx    = blockIdx.x;
    const int wt    = bx & 3;                 // W_/WT = 4 tiles
    const int h     = (bx >> 2) & (H_ - 1);
    const int b     = bx >> 10;               // /(4*256)
    const int wbase = wt * WT;
    const int tid   = threadIdx.x;

    const float* cbase = cost + ((size_t)(b * D_) * H_ + h) * W_ + wbase;
    const float* hbase = h1   + ((size_t)(b * C_) * H_ + h) * W_ + wbase;

    // ---- 1. zero A (covers out-of-band slots) ----
    {
        uint4 z = make_uint4(0u, 0u, 0u, 0u);
        #pragma unroll
        for (int i = 0; i < A_FLOATS / 4 / NTHREADS; i++)     // 8 iters
            ((uint4*)Af)[i * NTHREADS + tid] = z;
    }
    __syncthreads();

    // ---- 2. A band fill (strength-reduced) ----
    // A-block[mb][jj][kk] = tf32(cost[d][wbase + 16*mb + jj]), kk = jj + d,
    // d = dd*16 + seg.  16 == 0 mod 8 -> t, bit2 are dd-invariant and
    // ks = ks0 + 2*dd exactly, so the scatter address is one runtime base
    // plus compile-time immediates: each iter = LDG[imm] + CVT + STS[imm].
    {
        const int seg = tid >> 4;            // 0..15  (d = dd*16 + seg)
        const int jj  = tid & 15;
        const int kk0  = jj + seg;           // kk for dd=0
        const int t    = kk0 & 3;
        const int bit2 = (kk0 >> 2) & 1;
        const int ks0  = kk0 >> 3;           // +2 per dd
        const int g    = jj & 7, hi = jj >> 3;
        unsigned* abase =
            Af + (ks0 * 32 + g * 4 + t) * 4 + hi + 2 * bit2;  // + mb*1024 + dd*256
        const float* lbase = cbase + (size_t)seg * HW_ + jj;  // + dd*16*HW_ + mb*16

        #pragma unroll
        for (int mb = 0; mb < MB; mb++) {
            #pragma unroll
            for (int dd = 0; dd < 3; dd++) {
                unsigned v = tf32_of(lbase[(size_t)dd * (16 * HW_) + mb * 16]);
                abase[mb * 1024 + dd * 256] = v;
            }
        }
    }

    // ---- 3. B fill (strength-reduced) ----
    // B[k][c] = tf32(h1[c][wbase+k]) (0 beyond W); thread owns fixed (c, k8),
    // loops ch: both addresses are base + ch*const immediates.
    // frag scatter: addr = ch*384 + (g*4+t)*12 + 2*nt + j
    //   with t=k8&3, j=k8>>2, g=c&7, nt=c>>3
    {
        const int c  = tid >> 3;             // 0..31
        const int k8 = tid & 7;
        const int t = k8 & 3, j = k8 >> 2, g = c & 7, nt = c >> 3;
        unsigned* bdst = Bf + (g * 4 + t) * B_STRIDE + 2 * nt + j;
        const float* lsrc = hbase + (size_t)c * HW_ + k8;
        const int klim = W_ - wbase - k8;    // ch*8 < klim -> in bounds

        #pragma unroll
        for (int ch = 0; ch < KCH; ch++) {
            float fv = (ch * 8 < klim) ? lsrc[ch * 8] : 0.0f;
            bdst[ch * (32 * B_STRIDE)] = tf32_of(fv);
        }
    }
    __syncthreads();

    // ---- 4. mainloop: warp wid owns m-block wid (w rows 16*wid..+15) ----
    const int lane = tid & 31;
    const int wid  = tid >> 5;               // 0..7

    float acc[16];
    #pragma unroll
    for (int i = 0; i < 16; i++) acc[i] = 0.0f;

    const uint4* Ald = (const uint4*)Af + (wid * 8) * 32 + lane;
    const uint4* Bld = (const uint4*)(Bf + lane * B_STRIDE
                                         + (2 * wid) * (32 * B_STRIDE));

    #pragma unroll
    for (int ks = 0; ks < KS; ks++) {
        uint4 a  = Ald[ks * 32];                      // LDS.128, lane-major
        uint4 b0 = Bld[ks * (32 * B_STRIDE / 4)];     // words 0..3
        uint4 b1 = Bld[ks * (32 * B_STRIDE / 4) + 1]; // words 4..7
        mma8(acc + 0,  a.x, a.y, a.z, a.w, b0.x, b0.y);
        mma8(acc + 4,  a.x, a.y, a.z, a.w, b0.z, b0.w);
        mma8(acc + 8,  a.x, a.y, a.z, a.w, b1.x, b1.y);
        mma8(acc + 12, a.x, a.y, a.z, a.w, b1.z, b1.w);
    }

    // ---- 5. epilogue: D[g][2t] layout -> out[c][w] scatter ----
    // d0:(w=+g, c), d1:(+g, c+1), d2:(+g+8, c), d3:(+g+8, c+1)
    {
        const int g = lane >> 2, t = lane & 3;
        const int w = wbase + wid * 16 + g;
        float* obase = out + ((size_t)(b * C_) * H_ + h) * W_;
        #pragma unroll
        for (int nt = 0; nt < 4; nt++) {
            int c = nt * 8 + t * 2;
            float* p = obase + (size_t)c * HW_ + w;
            p[0]       = acc[nt * 4 + 0];
            p[HW_]     = acc[nt * 4 + 1];
            p[8]       = acc[nt * 4 + 2];
            p[HW_ + 8] = acc[nt * 4 + 3];
        }
    }
}

extern "C" void kernel_launch(void* const* d_in, const int* in_sizes, int n_in,
                              void* d_out, int out_size) {
    (void)in_sizes; (void)n_in; (void)out_size;
    const float* h1   = (const float*)d_in[0];
    const float* cost = (const float*)d_in[1];
    float* out        = (float*)d_out;

    // >48KB static limit -> dynamic smem (attribute set is idempotent,
    // not a stream op, and performs no allocation)
    cudaFuncSetAttribute(dense_warp_kernel,
                         cudaFuncAttributeMaxDynamicSharedMemorySize,
                         SMEM_BYTES);

    const int nblocks = B_ * H_ * (W_ / WT);   // 4096
    dense_warp_kernel<<<nblocks, NTHREADS, SMEM_BYTES>>>(h1, cost, out);
}